// round 1
// baseline (speedup 1.0000x reference)
#include <cuda_runtime.h>
#include <math.h>

#define BATCH 4
#define SEQ   4096
#define DIM   1024

// ---- scratch (no cudaMalloc allowed) ----
__device__ float g_q[BATCH * SEQ * DIM];
__device__ float g_k[BATCH * SEQ * DIM];
__device__ float g_v[BATCH * SEQ * DIM];
__device__ float g_ctx[BATCH * SEQ * DIM];
__device__ float g_sc[(size_t)BATCH * SEQ * SEQ];   // 256 MB scores/probs

// ---------------------------------------------------------------------------
// Generic 128x128 tile SGEMM, BK=8, 256 threads, 8x8 accum per thread.
//   NT      : B is [N,K] row-major and we compute A @ B^T  (else B is [K,N])
//   CAUSAL  : skip blocks entirely above the diagonal (scores GEMM)
//   KLIMIT  : limit K loop to row_tile_end+1 (P@V causal GEMM)
//   HAS_BIAS: add bias[n]
//   SCALE   : multiply result by `scale`
// All dims must be multiples of tile sizes (true here: 16384/4096/1024, K%8==0).
// ---------------------------------------------------------------------------
template<bool NT, bool CAUSAL, bool KLIMIT, bool HAS_BIAS, bool SCALE>
__global__ __launch_bounds__(256)
void gemm128(const float* __restrict__ A, const float* __restrict__ Bm,
             const float* __restrict__ bias, float* __restrict__ C,
             int M, int N, int K, float scale,
             long sA, long sB, long sC)
{
    const int bz = blockIdx.z;
    A  += (long)bz * sA;
    Bm += (long)bz * sB;
    C  += (long)bz * sC;

    const int row0 = blockIdx.y * 128;
    const int col0 = blockIdx.x * 128;
    if (CAUSAL && col0 > row0) return;   // tile fully above diagonal

    int Keff = K;
    if (KLIMIT) {
        int lim = row0 + 128;
        Keff = lim < K ? lim : K;
    }

    __shared__ float As[8][128];
    __shared__ float Bs[8][128];

    const int t = threadIdx.x;

    // A-tile loader mapping (also reused for NT B-tile): one float4 per thread
    const int a_row = t >> 1;          // 0..127
    const int a_col = (t & 1) * 4;     // 0 or 4
    // B-tile loader mapping for NN
    const int b_row = t >> 5;          // 0..7
    const int b_col = (t & 31) * 4;    // 0..124

    const int ty = t >> 4;             // 0..15
    const int tx = t & 15;             // 0..15
    const int rbase = ty * 8;
    const int cbase = tx * 8;

    float acc[8][8];
    #pragma unroll
    for (int i = 0; i < 8; i++)
        #pragma unroll
        for (int j = 0; j < 8; j++) acc[i][j] = 0.f;

    const float* Aptr = A + (long)(row0 + a_row) * K + a_col;
    const float* Bptr = NT ? (Bm + (long)(col0 + a_row) * K + a_col)
                           : (Bm + (long)b_row * N + col0 + b_col);

    for (int k0 = 0; k0 < Keff; k0 += 8) {
        float4 av = *(const float4*)(Aptr + k0);
        As[a_col + 0][a_row] = av.x;
        As[a_col + 1][a_row] = av.y;
        As[a_col + 2][a_row] = av.z;
        As[a_col + 3][a_row] = av.w;
        if (NT) {
            float4 bv = *(const float4*)(Bptr + k0);
            Bs[a_col + 0][a_row] = bv.x;
            Bs[a_col + 1][a_row] = bv.y;
            Bs[a_col + 2][a_row] = bv.z;
            Bs[a_col + 3][a_row] = bv.w;
        } else {
            float4 bv = *(const float4*)(Bptr + (long)k0 * N);
            *(float4*)&Bs[b_row][b_col] = bv;
        }
        __syncthreads();

        #pragma unroll
        for (int kk = 0; kk < 8; kk++) {
            float ar[8], br[8];
            *(float4*)(ar)     = *(const float4*)&As[kk][rbase];
            *(float4*)(ar + 4) = *(const float4*)&As[kk][rbase + 4];
            *(float4*)(br)     = *(const float4*)&Bs[kk][cbase];
            *(float4*)(br + 4) = *(const float4*)&Bs[kk][cbase + 4];
            #pragma unroll
            for (int i = 0; i < 8; i++)
                #pragma unroll
                for (int j = 0; j < 8; j++)
                    acc[i][j] += ar[i] * br[j];
        }
        __syncthreads();
    }

    float bb[8];
    if (HAS_BIAS) {
        #pragma unroll
        for (int j = 0; j < 8; j++) bb[j] = bias[col0 + cbase + j];
    }

    #pragma unroll
    for (int i = 0; i < 8; i++) {
        float* cp = C + (long)(row0 + rbase + i) * N + col0 + cbase;
        float tmp[8];
        #pragma unroll
        for (int j = 0; j < 8; j++) {
            float v = acc[i][j];
            if (SCALE)    v *= scale;
            if (HAS_BIAS) v += bb[j];
            tmp[j] = v;
        }
        *(float4*)(cp)     = make_float4(tmp[0], tmp[1], tmp[2], tmp[3]);
        *(float4*)(cp + 4) = make_float4(tmp[4], tmp[5], tmp[6], tmp[7]);
    }
}

// ---------------------------------------------------------------------------
// Causal softmax over scores, in place.  One block per row.
// Row (b, i): valid entries j in [0, i]; zero-fill (i, roundup128(i+1)) so the
// causal P@V GEMM can run full 128-wide k-tiles.
// ---------------------------------------------------------------------------
__global__ __launch_bounds__(256)
void softmax_causal(float* __restrict__ sc)
{
    const long row = blockIdx.x;
    const int  b   = (int)(row >> 12);       // row / 4096
    const int  i   = (int)(row & 4095);
    float* p = sc + (long)b * SEQ * SEQ + (long)i * SEQ;
    const int L = i + 1;
    const int t = threadIdx.x;

    __shared__ float red[256];

    float m = -1e30f;
    for (int j = t; j < L; j += 256) m = fmaxf(m, p[j]);
    red[t] = m; __syncthreads();
    for (int s = 128; s > 0; s >>= 1) {
        if (t < s) red[t] = fmaxf(red[t], red[t + s]);
        __syncthreads();
    }
    m = red[0]; __syncthreads();

    float sum = 0.f;
    for (int j = t; j < L; j += 256) sum += __expf(p[j] - m);
    red[t] = sum; __syncthreads();
    for (int s = 128; s > 0; s >>= 1) {
        if (t < s) red[t] += red[t + s];
        __syncthreads();
    }
    const float inv = 1.0f / red[0];
    __syncthreads();

    const int Lpad = (L + 127) & ~127;
    for (int j = t; j < Lpad; j += 256)
        p[j] = (j < L) ? __expf(p[j] - m) * inv : 0.f;
}

// ---------------------------------------------------------------------------
extern "C" void kernel_launch(void* const* d_in, const int* in_sizes, int n_in,
                              void* d_out, int out_size)
{
    const float* x  = (const float*)d_in[0];
    const float* Wq = (const float*)d_in[1];
    const float* bq = (const float*)d_in[2];
    const float* Wk = (const float*)d_in[3];
    const float* bk = (const float*)d_in[4];
    const float* Wv = (const float*)d_in[5];
    const float* bv = (const float*)d_in[6];
    const float* Wo = (const float*)d_in[7];
    const float* bo = (const float*)d_in[8];
    float* out = (float*)d_out;

    float *q, *k, *v, *ctx, *sc;
    cudaGetSymbolAddress((void**)&q,   g_q);
    cudaGetSymbolAddress((void**)&k,   g_k);
    cudaGetSymbolAddress((void**)&v,   g_v);
    cudaGetSymbolAddress((void**)&ctx, g_ctx);
    cudaGetSymbolAddress((void**)&sc,  g_sc);

    const int M = BATCH * SEQ;                  // 16384
    const float scale = 1.0f / sqrtf((float)DIM);

    // 1) Q, K, V projections: [16384,1024] @ [1024,1024] + bias
    {
        dim3 grid(DIM / 128, M / 128, 1);
        gemm128<false, false, false, true, false><<<grid, 256>>>(
            x, Wq, bq, q, M, DIM, DIM, 1.f, 0, 0, 0);
        gemm128<false, false, false, true, false><<<grid, 256>>>(
            x, Wk, bk, k, M, DIM, DIM, 1.f, 0, 0, 0);
        gemm128<false, false, false, true, false><<<grid, 256>>>(
            x, Wv, bv, v, M, DIM, DIM, 1.f, 0, 0, 0);
    }

    // 2) scores = q @ k^T * scale  (per batch, lower-triangular tiles only)
    {
        dim3 grid(SEQ / 128, SEQ / 128, BATCH);
        gemm128<true, true, false, false, true><<<grid, 256>>>(
            q, k, nullptr, sc, SEQ, SEQ, DIM, scale,
            (long)SEQ * DIM, (long)SEQ * DIM, (long)SEQ * SEQ);
    }

    // 3) causal softmax in place
    softmax_causal<<<BATCH * SEQ, 256>>>(sc);

    // 4) ctx = P @ v  (per batch, k-loop limited to causal range)
    {
        dim3 grid(DIM / 128, SEQ / 128, BATCH);
        gemm128<false, false, true, false, false><<<grid, 256>>>(
            sc, v, nullptr, ctx, SEQ, DIM, SEQ, 1.f,
            (long)SEQ * SEQ, (long)SEQ * DIM, (long)SEQ * DIM);
    }

    // 5) out = ctx @ Wo + bo
    {
        dim3 grid(DIM / 128, M / 128, 1);
        gemm128<false, false, false, true, false><<<grid, 256>>>(
            ctx, Wo, bo, out, M, DIM, DIM, 1.f, 0, 0, 0);
    }
}